// round 6
// baseline (speedup 1.0000x reference)
#include <cuda_runtime.h>
#include <cuda_bf16.h>

// Problem constants (fixed shapes from reference)
#define T_LEN   4096
#define C_IN    8
#define BATCH   64
#define D_MODEL 128
#define N_STATE 64
#define HID     128
#define CB_ROWS (C_IN*BATCH)    // 512

// Decay negligibility threshold: terms with a^k < e^-THRESH are dropped.
// Tail bound: e^-34/(1-a_max) * |cb| * |u| * 64  ~ 1e-10 on y ~ O(1).
#define THRESH  34.0f

// GEMM tiling: 128x128 block tile, 16x8 per thread (compute-bound ratio)
#define NSPLIT  64
#define TSEG    (T_LEN/NSPLIT)  // 64
#define KC      16
#define RT      128             // rows per block tile

// Decay: one block covers DK consecutive k for all 128 d
#define DK      16

// Scratch (no allocations allowed -> device globals, zero-initialized once)
__device__ float g_buf[T_LEN*D_MODEL];                 // g[t][d], 2 MB
__device__ float gs_buf[D_MODEL];                      // Gs[d]
__device__ float p_part[NSPLIT*CB_ROWS*D_MODEL];       // k-split partials
__device__ float P_buf[CB_ROWS*D_MODEL];               // reduced P, 256 KB
__device__ float lna_tab[D_MODEL*N_STATE];             // ln(sigmoid(log_a))
__device__ float a_tab[D_MODEL*N_STATE];               // sigmoid(log_a)
__device__ float cb_tab[D_MODEL*N_STATE];              // C*B
__device__ int   kcut;                                 // max non-negligible k
// kcut via atomicMax w/o reset: inputs constant across graph replays ->
// monotone & identical every call (deterministic).

__device__ __forceinline__ int split_lo(int kc) {
    // smallest split s whose k-range [T-TSEG*(s+1), T-TSEG*s) intersects k<=kc
    int s0 = (T_LEN - kc + TSEG - 1) / TSEG - 1;
    return s0 < 0 ? 0 : s0;
}

// ---------------------------------------------------------------------------
// Kernel 0: tables + Gs[d] (exact geometric series) + global kcut.
// ---------------------------------------------------------------------------
__global__ void prep_kernel(const float* __restrict__ log_a,
                            const float* __restrict__ B_ssm,
                            const float* __restrict__ C_ssm) {
    const int d = blockIdx.x;
    const int n = threadIdx.x;

    float la  = log_a[d*N_STATE + n];
    float a   = 1.f / (1.f + expf(-la));     // accurate sigmoid
    float lna = logf(a);                     // < 0
    float cb  = C_ssm[d*N_STATE + n] * B_ssm[d*N_STATE + n];
    lna_tab[d*N_STATE + n] = lna;
    a_tab  [d*N_STATE + n] = a;
    cb_tab [d*N_STATE + n] = cb;

    int km = (lna > -1e-6f) ? T_LEN
                            : min(T_LEN, (int)(THRESH / -lna) + 1);

    float aT  = __expf((float)T_LEN * lna);
    float gsn = cb * (1.f - aT) / fmaxf(1.f - a, 1e-30f);

    __shared__ float gs_sh[N_STATE];
    __shared__ int   km_sh[N_STATE];
    gs_sh[n] = gsn;
    km_sh[n] = km;
    __syncthreads();
    if (n == 0) {
        float s = 0.f; int m = 0;
        #pragma unroll
        for (int i = 0; i < N_STATE; ++i) { s += gs_sh[i]; m = max(m, km_sh[i]); }
        gs_buf[d] = s;
        atomicMax(&kcut, m);
    }
}

// ---------------------------------------------------------------------------
// Kernel 1: g[d,t] = sum_n cb * a^(T-1-t). THREAD-PER-D layout: block covers
// k in [kb, kb+DK) for all 128 d. One __expf anchor per (d,n,chunk) + DK-1
// multiplies. Stores for fixed j are 128 consecutive floats -> coalesced.
// Chunks beyond kcut never written: zero-init content IS the correct value.
// ---------------------------------------------------------------------------
__global__ void decay_kernel() {
    const int kb = blockIdx.x * DK;
    if (kb > kcut) return;

    const int d = threadIdx.x;            // 128 threads = 128 d
    const float kbf = (float)kb;

    const float* lna_p = lna_tab + d*N_STATE;
    const float* a_p   = a_tab   + d*N_STATE;
    const float* cb_p  = cb_tab  + d*N_STATE;

    float acc[DK];
    #pragma unroll
    for (int j = 0; j < DK; ++j) acc[j] = 0.f;

    #pragma unroll 2
    for (int n = 0; n < N_STATE; ++n) {
        float lna = lna_p[n];
        if (kbf * lna > -THRESH) {
            float a  = a_p[n];
            float cb = cb_p[n];
            float e  = __expf(kbf * lna);
            #pragma unroll
            for (int j = 0; j < DK; ++j) { acc[j] += cb * e; e *= a; }
        }
    }
    #pragma unroll
    for (int j = 0; j < DK; ++j) {
        int t = T_LEN - 1 - (kb + j);
        g_buf[t*D_MODEL + d] = acc[j];    // coalesced across d
    }
}

// ---------------------------------------------------------------------------
// Kernel 2: P_part[s] = X[rows, t-seg(s)] @ G[t-seg(s), D]
// X = in_chan viewed as [512, 4096]. 128x128 block tile, 16x8 per thread
// (1.33 FMA/byte of smem -> compute-bound). grid (NSPLIT, 4).
// ---------------------------------------------------------------------------
__global__ void __launch_bounds__(128) gemm_kernel(const float* __restrict__ X) {
    const int split = blockIdx.x;
    if (split < split_lo(kcut)) return;

    const int rowbase = blockIdx.y * RT;
    const int tid     = threadIdx.x;

    __shared__ __align__(16) float As[KC][RT];       // 8 KB
    __shared__ __align__(16) float Bs[KC][D_MODEL];  // 8 KB

    float acc[16][8];
    #pragma unroll
    for (int i = 0; i < 16; ++i)
        #pragma unroll
        for (int j = 0; j < 8; ++j) acc[i][j] = 0.f;

    const int r0 = (tid >> 4) * 16;    // 8 row-groups of 16
    const int c0 = (tid & 15) * 8;     // 16 col-groups of 8
    const int bc  = (tid & 31) * 4;    // B-load col
    const int bk0 = tid >> 5;          // B-load k base

    #pragma unroll
    for (int ch = 0; ch < TSEG/KC; ++ch) {
        const int tb = split*TSEG + ch*KC;

        // A tile: thread loads 16 k of row `tid` (4 x LDG.128), transposes
        const float* asrc = X + (rowbase + tid)*T_LEN + tb;
        float4 v0 = *(const float4*)(asrc);
        float4 v1 = *(const float4*)(asrc + 4);
        float4 v2 = *(const float4*)(asrc + 8);
        float4 v3 = *(const float4*)(asrc + 12);
        As[ 0][tid] = v0.x; As[ 1][tid] = v0.y; As[ 2][tid] = v0.z; As[ 3][tid] = v0.w;
        As[ 4][tid] = v1.x; As[ 5][tid] = v1.y; As[ 6][tid] = v1.z; As[ 7][tid] = v1.w;
        As[ 8][tid] = v2.x; As[ 9][tid] = v2.y; As[10][tid] = v2.z; As[11][tid] = v2.w;
        As[12][tid] = v3.x; As[13][tid] = v3.y; As[14][tid] = v3.z; As[15][tid] = v3.w;

        // B tile: coalesced float4
        #pragma unroll
        for (int it = 0; it < 4; ++it) {
            int kk = it*4 + bk0;
            *(float4*)&Bs[kk][bc] =
                *(const float4*)(g_buf + (tb + kk)*D_MODEL + bc);
        }
        __syncthreads();

        #pragma unroll
        for (int kk = 0; kk < KC; ++kk) {
            float4 a0 = *(const float4*)&As[kk][r0];
            float4 a1 = *(const float4*)&As[kk][r0+4];
            float4 a2 = *(const float4*)&As[kk][r0+8];
            float4 a3 = *(const float4*)&As[kk][r0+12];
            float4 b0 = *(const float4*)&Bs[kk][c0];
            float4 b1 = *(const float4*)&Bs[kk][c0+4];
            float av[16] = {a0.x,a0.y,a0.z,a0.w, a1.x,a1.y,a1.z,a1.w,
                            a2.x,a2.y,a2.z,a2.w, a3.x,a3.y,a3.z,a3.w};
            float bv[8]  = {b0.x,b0.y,b0.z,b0.w, b1.x,b1.y,b1.z,b1.w};
            #pragma unroll
            for (int i = 0; i < 16; ++i)
                #pragma unroll
                for (int j = 0; j < 8; ++j)
                    acc[i][j] += av[i] * bv[j];
        }
        __syncthreads();
    }

    float* base = p_part + split*CB_ROWS*D_MODEL;
    #pragma unroll
    for (int i = 0; i < 16; ++i) {
        float4 o0 = make_float4(acc[i][0], acc[i][1], acc[i][2], acc[i][3]);
        float4 o1 = make_float4(acc[i][4], acc[i][5], acc[i][6], acc[i][7]);
        float* dst = base + (rowbase + r0 + i)*D_MODEL + c0;
        *(float4*)dst       = o0;
        *(float4*)(dst + 4) = o1;
    }
}

// ---------------------------------------------------------------------------
// Kernel 3: reduce active split partials -> P_buf [512][128].
// s-dimension parallelized ACROSS threads: grid 512 (one block per row),
// 256 threads = 2 s-groups x 128 d; smem combine. 4096 warps chip-wide.
// ---------------------------------------------------------------------------
__global__ void reduce_kernel() {
    const int row = blockIdx.x;
    const int tid = threadIdx.x;
    const int sg  = tid >> 7;                 // 0..1
    const int d   = tid & 127;
    const int s0  = split_lo(kcut);
    const int stride = CB_ROWS*D_MODEL;

    float a0 = 0.f, a1 = 0.f;
    int s = s0 + sg;
    for (; s + 2 < NSPLIT; s += 4) {          // 2-way ILP per thread
        a0 += p_part[s*stride     + row*D_MODEL + d];
        a1 += p_part[(s+2)*stride + row*D_MODEL + d];
    }
    for (; s < NSPLIT; s += 2)
        a0 += p_part[s*stride + row*D_MODEL + d];

    __shared__ float rs[256];
    rs[tid] = a0 + a1;
    __syncthreads();
    if (tid < 128)
        P_buf[row*D_MODEL + tid] = rs[tid] + rs[tid + 128];
}

// ---------------------------------------------------------------------------
// Kernel 4: epilogue. One block per batch b, 128 threads.
// ---------------------------------------------------------------------------
__global__ void final_kernel(const float* __restrict__ in_chan,
                             const float* __restrict__ W_in,
                             const float* __restrict__ b_in,
                             const float* __restrict__ D_ssm,
                             const float* __restrict__ W_mu,
                             const float* __restrict__ b_mu,
                             const float* __restrict__ W_lin,
                             const float* __restrict__ b_lin,
                             float* __restrict__ out) {
    const int b   = blockIdx.x;
    const int tid = threadIdx.x;

    __shared__ float m_sh[C_IN];
    __shared__ float ysh[D_MODEL];
    __shared__ float red[4];

    if (tid < C_IN)
        m_sh[tid] = in_chan[(tid*BATCH + b)*T_LEN + (T_LEN-1)];
    __syncthreads();

    float bi = b_in[tid];
    float y  = bi * gs_buf[tid];
    float ul = bi;
    #pragma unroll
    for (int c = 0; c < C_IN; ++c) {
        float m = m_sh[c];
        float w = W_in[c*D_MODEL + tid];
        float p = P_buf[(c*BATCH + b)*D_MODEL + tid];
        y  += m * w * p;
        ul += m * m * w;
    }
    y += D_ssm[tid] * ul;

    // gelu (tanh approximation, matching jax.nn.gelu default)
    float tg  = 0.7978845608028654f * (y + 0.044715f*y*y*y);
    float gel = 0.5f * y * (1.f + tanhf(tg));
    ysh[tid] = gel;
    __syncthreads();

    float z = b_mu[tid];
    #pragma unroll 8
    for (int dd = 0; dd < D_MODEL; ++dd)
        z += ysh[dd] * W_mu[dd*HID + tid];

    float v = z * W_lin[tid];
    #pragma unroll
    for (int o = 16; o; o >>= 1)
        v += __shfl_down_sync(0xffffffffu, v, o);
    if ((tid & 31) == 0) red[tid >> 5] = v;
    __syncthreads();
    if (tid == 0) {
        float s = red[0] + red[1] + red[2] + red[3] + b_lin[0];
        out[b] = 1.f / (1.f + expf(-s));
    }
}

// ---------------------------------------------------------------------------
extern "C" void kernel_launch(void* const* d_in, const int* in_sizes, int n_in,
                              void* d_out, int out_size) {
    const float* in_chan = (const float*)d_in[0];
    // d_in[1] = h_0, d_in[2] = c_0 : unused (zeros)
    const float* W_in  = (const float*)d_in[3];
    const float* b_in  = (const float*)d_in[4];
    const float* log_a = (const float*)d_in[5];
    const float* B_ssm = (const float*)d_in[6];
    const float* C_ssm = (const float*)d_in[7];
    const float* D_ssm = (const float*)d_in[8];
    const float* W_mu  = (const float*)d_in[9];
    const float* b_mu  = (const float*)d_in[10];
    const float* W_lin = (const float*)d_in[11];
    const float* b_lin = (const float*)d_in[12];
    float* out = (float*)d_out;

    prep_kernel  <<<D_MODEL, N_STATE>>>(log_a, B_ssm, C_ssm);
    decay_kernel <<<T_LEN/DK, D_MODEL>>>();
    gemm_kernel  <<<dim3(NSPLIT, CB_ROWS/RT), 128>>>(in_chan);
    reduce_kernel<<<CB_ROWS, 256>>>();
    final_kernel <<<BATCH, D_MODEL>>>(in_chan, W_in, b_in, D_ssm,
                                      W_mu, b_mu, W_lin, b_lin, out);
}

// round 7
// speedup vs baseline: 2.0307x; 2.0307x over previous
#include <cuda_runtime.h>
#include <cuda_bf16.h>

// Problem constants (fixed shapes from reference)
#define T_LEN   4096
#define C_IN    8
#define BATCH   64
#define D_MODEL 128
#define N_STATE 64
#define HID     128
#define CB_ROWS (C_IN*BATCH)    // 512

// Decay negligibility threshold: terms with a^k < e^-THRESH are dropped.
// Tail bound: e^-34/(1-a_max) * |cb| * |u| * 64  ~ 1e-10 on y ~ O(1).
#define THRESH  34.0f

// GEMM tiling (R3 measured-best config)
#define NSPLIT  64
#define TSEG    (T_LEN/NSPLIT)  // 64
#define KC      16
#define RT      64

// Scratch (no allocations allowed -> device globals, zero-initialized once)
__device__ float g_buf[T_LEN*D_MODEL];                 // g[t][d], 2 MB
__device__ float gs_buf[D_MODEL];                      // Gs[d]
__device__ float Y_part[NSPLIT*BATCH*D_MODEL];         // folded partials, 2 MB
__device__ float lna_tab[D_MODEL*N_STATE];             // ln(sigmoid(log_a))
__device__ float cb_tab[D_MODEL*N_STATE];              // C*B
__device__ int   kcut;                                 // max non-negligible k
// kcut via atomicMax w/o reset: inputs constant across graph replays ->
// monotone & identical every call (deterministic).

__device__ __forceinline__ int split_lo(int kc) {
    // smallest split s whose k-range [T-TSEG*(s+1), T-TSEG*s) intersects k<=kc
    int s0 = (T_LEN - kc + TSEG - 1) / TSEG - 1;
    return s0 < 0 ? 0 : s0;
}

// ---------------------------------------------------------------------------
// Kernel 0: tables + Gs[d] (exact geometric series) + global kcut.
// ---------------------------------------------------------------------------
__global__ void prep_kernel(const float* __restrict__ log_a,
                            const float* __restrict__ B_ssm,
                            const float* __restrict__ C_ssm) {
    const int d = blockIdx.x;
    const int n = threadIdx.x;

    float la  = log_a[d*N_STATE + n];
    float a   = 1.f / (1.f + expf(-la));     // accurate sigmoid
    float lna = logf(a);                     // < 0
    float cb  = C_ssm[d*N_STATE + n] * B_ssm[d*N_STATE + n];
    lna_tab[d*N_STATE + n] = lna;
    cb_tab [d*N_STATE + n] = cb;

    int km = (lna > -1e-6f) ? T_LEN
                            : min(T_LEN, (int)(THRESH / -lna) + 1);

    float aT  = __expf((float)T_LEN * lna);
    float gsn = cb * (1.f - aT) / fmaxf(1.f - a, 1e-30f);

    __shared__ float gs_sh[N_STATE];
    __shared__ int   km_sh[N_STATE];
    gs_sh[n] = gsn;
    km_sh[n] = km;
    __syncthreads();
    if (n == 0) {
        float s = 0.f; int m = 0;
        #pragma unroll
        for (int i = 0; i < N_STATE; ++i) { s += gs_sh[i]; m = max(m, km_sh[i]); }
        gs_buf[d] = s;
        atomicMax(&kcut, m);
    }
}

// ---------------------------------------------------------------------------
// Kernel 1 (R3 config): g[d,t] = sum_n cb * a^(T-1-t). Chunks beyond kcut
// never written: zero-init content IS the (negligible->0) correct value.
// grid = (T/128, D_MODEL), 128 threads.
// ---------------------------------------------------------------------------
__global__ void decay_kernel() {
    const int kmin = blockIdx.x * 128;
    if (kmin > kcut) return;

    const int d   = blockIdx.y;
    const int tid = threadIdx.x;

    __shared__ float lna_s[N_STATE];
    __shared__ float cb_s[N_STATE];
    if (tid < N_STATE) {
        lna_s[tid] = lna_tab[d*N_STATE + tid];
        cb_s[tid]  = cb_tab [d*N_STATE + tid];
    }
    __syncthreads();

    const float kminf = (float)kmin;
    const float kf    = (float)(kmin + tid);

    float acc = 0.f;
    #pragma unroll 4
    for (int n = 0; n < N_STATE; ++n) {
        float lna = lna_s[n];
        if (kminf * lna > -THRESH) {            // block-uniform per n
            acc += cb_s[n] * __expf(kf * lna);
        }
    }
    const int t = T_LEN - 1 - (kmin + tid);
    g_buf[t*D_MODEL + d] = acc;
}

// ---------------------------------------------------------------------------
// Kernel 2: fused GEMM + c-fold.
// Block rows are B-MAJOR: local row r in [0,64) maps to X row (r&7)*64 + b,
// b = b8 + (r>>3). So each thread's acc[8][8] = P[(b, c=0..7), 8 cols] for ONE
// b, and the epilogue folds sum_c m[b,c]*W_in[c,d]*P directly in registers.
// Output per (split, block): Y_part[split][b8..b8+8][128]  (1K floats).
// ---------------------------------------------------------------------------
__global__ void __launch_bounds__(128) gemm_kernel(const float* __restrict__ X,
                                                   const float* __restrict__ W_in) {
    const int split = blockIdx.x;
    if (split < split_lo(kcut)) return;

    const int b8  = blockIdx.y * 8;          // 8 batches per block
    const int tid = threadIdx.x;

    __shared__ __align__(16) float As[KC][RT];        // 4 KB
    __shared__ __align__(16) float Bs[KC][D_MODEL];   // 8 KB
    __shared__ __align__(16) float w_sh[C_IN][D_MODEL]; // 4 KB
    __shared__ float m_sh[8][C_IN];                   // [b_local][c]

    // Stage W_in (coalesced) and m = X[:, T-1] for this block's 8 b's.
    #pragma unroll
    for (int i = 0; i < 8; ++i)
        ((float*)w_sh)[tid + i*128] = W_in[tid + i*128];
    if (tid < 64) {
        int c  = tid & 7;
        int bl = tid >> 3;
        m_sh[bl][c] = X[((c << 6) + b8 + bl)*T_LEN + (T_LEN - 1)];
    }

    float acc[8][8];
    #pragma unroll
    for (int i = 0; i < 8; ++i)
        #pragma unroll
        for (int j = 0; j < 8; ++j) acc[i][j] = 0.f;

    const int r0  = (tid >> 4) * 8;    // local rows r0..r0+7 = one b, c=0..7
    const int c0  = (tid & 15) * 8;
    const int ar  = tid >> 1;          // A-load local row
    const int ak  = (tid & 1) * 8;     // A-load k offset
    const int bc  = (tid & 31) * 4;    // B-load col
    const int bk0 = tid >> 5;          // B-load k base
    const int xrow = ((ar & 7) << 6) + b8 + (ar >> 3);   // b-major permutation

    #pragma unroll
    for (int ch = 0; ch < TSEG/KC; ++ch) {
        const int tb = split*TSEG + ch*KC;

        const float* asrc = X + xrow*T_LEN + tb + ak;
        float4 v0 = *(const float4*)asrc;
        float4 v1 = *(const float4*)(asrc + 4);
        As[ak+0][ar] = v0.x; As[ak+1][ar] = v0.y;
        As[ak+2][ar] = v0.z; As[ak+3][ar] = v0.w;
        As[ak+4][ar] = v1.x; As[ak+5][ar] = v1.y;
        As[ak+6][ar] = v1.z; As[ak+7][ar] = v1.w;

        #pragma unroll
        for (int it = 0; it < 4; ++it) {
            int kk = it*4 + bk0;
            *(float4*)&Bs[kk][bc] =
                *(const float4*)(g_buf + (tb + kk)*D_MODEL + bc);
        }
        __syncthreads();

        #pragma unroll
        for (int kk = 0; kk < KC; ++kk) {
            float4 a0 = *(const float4*)&As[kk][r0];
            float4 a1 = *(const float4*)&As[kk][r0+4];
            float4 b0 = *(const float4*)&Bs[kk][c0];
            float4 b1 = *(const float4*)&Bs[kk][c0+4];
            float av[8] = {a0.x,a0.y,a0.z,a0.w,a1.x,a1.y,a1.z,a1.w};
            float bv[8] = {b0.x,b0.y,b0.z,b0.w,b1.x,b1.y,b1.z,b1.w};
            #pragma unroll
            for (int i = 0; i < 8; ++i)
                #pragma unroll
                for (int j = 0; j < 8; ++j)
                    acc[i][j] += av[i] * bv[j];
        }
        __syncthreads();
    }

    // c-fold epilogue: yo[j] = sum_c m[b,c] * W_in[c, c0+j] * acc[c][j]
    const int bl = tid >> 4;           // b_local (= r0/8)
    float yo[8];
    #pragma unroll
    for (int j = 0; j < 8; ++j) yo[j] = 0.f;
    #pragma unroll
    for (int c = 0; c < C_IN; ++c) {
        float m = m_sh[bl][c];
        float4 w0 = *(const float4*)&w_sh[c][c0];
        float4 w1 = *(const float4*)&w_sh[c][c0+4];
        float wv[8] = {w0.x,w0.y,w0.z,w0.w, w1.x,w1.y,w1.z,w1.w};
        #pragma unroll
        for (int j = 0; j < 8; ++j)
            yo[j] += m * wv[j] * acc[c][j];
    }
    float* dst = Y_part + (split*BATCH + b8 + bl)*D_MODEL + c0;
    *(float4*)dst       = make_float4(yo[0], yo[1], yo[2], yo[3]);
    *(float4*)(dst + 4) = make_float4(yo[4], yo[5], yo[6], yo[7]);
}

// ---------------------------------------------------------------------------
// Kernel 3: epilogue. One block per batch b, 128 threads (= d = hid index).
// y[b,d] = sum_{s>=s0} Y_part[s][b][d] + b_in*Gs + D*(sum_c m^2*W_in + b_in)
// z = gelu_tanh(y) @ W_mu + b_mu ; out[b] = sigmoid(z . W_lin + b_lin)
// ---------------------------------------------------------------------------
__global__ void final_kernel(const float* __restrict__ in_chan,
                             const float* __restrict__ W_in,
                             const float* __restrict__ b_in,
                             const float* __restrict__ D_ssm,
                             const float* __restrict__ W_mu,
                             const float* __restrict__ b_mu,
                             const float* __restrict__ W_lin,
                             const float* __restrict__ b_lin,
                             float* __restrict__ out) {
    const int b   = blockIdx.x;
    const int tid = threadIdx.x;

    __shared__ float m_sh[C_IN];
    __shared__ float ysh[D_MODEL];
    __shared__ float red[4];

    if (tid < C_IN)
        m_sh[tid] = in_chan[(tid*BATCH + b)*T_LEN + (T_LEN-1)];
    __syncthreads();

    // Sum folded split partials (4-way ILP to cover L2 latency).
    const int s0 = split_lo(kcut);
    const int stride = BATCH*D_MODEL;
    const float* yp = Y_part + b*D_MODEL + tid;
    float a0 = 0.f, a1 = 0.f, a2 = 0.f, a3 = 0.f;
    int s = s0;
    for (; s + 4 <= NSPLIT; s += 4) {
        a0 += yp[(s+0)*stride];
        a1 += yp[(s+1)*stride];
        a2 += yp[(s+2)*stride];
        a3 += yp[(s+3)*stride];
    }
    for (; s < NSPLIT; ++s) a0 += yp[s*stride];

    float bi = b_in[tid];
    float y  = bi * gs_buf[tid] + (a0 + a1) + (a2 + a3);

    float ul = bi;
    #pragma unroll
    for (int c = 0; c < C_IN; ++c)
        ul += m_sh[c] * m_sh[c] * W_in[c*D_MODEL + tid];
    y += D_ssm[tid] * ul;

    // gelu (tanh approximation, matching jax.nn.gelu default)
    float tg  = 0.7978845608028654f * (y + 0.044715f*y*y*y);
    float gel = 0.5f * y * (1.f + tanhf(tg));
    ysh[tid] = gel;
    __syncthreads();

    float z = b_mu[tid];
    #pragma unroll 8
    for (int dd = 0; dd < D_MODEL; ++dd)
        z += ysh[dd] * W_mu[dd*HID + tid];

    float v = z * W_lin[tid];
    #pragma unroll
    for (int o = 16; o; o >>= 1)
        v += __shfl_down_sync(0xffffffffu, v, o);
    if ((tid & 31) == 0) red[tid >> 5] = v;
    __syncthreads();
    if (tid == 0) {
        float s2 = red[0] + red[1] + red[2] + red[3] + b_lin[0];
        out[b] = 1.f / (1.f + expf(-s2));
    }
}

// ---------------------------------------------------------------------------
extern "C" void kernel_launch(void* const* d_in, const int* in_sizes, int n_in,
                              void* d_out, int out_size) {
    const float* in_chan = (const float*)d_in[0];
    // d_in[1] = h_0, d_in[2] = c_0 : unused (zeros)
    const float* W_in  = (const float*)d_in[3];
    const float* b_in  = (const float*)d_in[4];
    const float* log_a = (const float*)d_in[5];
    const float* B_ssm = (const float*)d_in[6];
    const float* C_ssm = (const float*)d_in[7];
    const float* D_ssm = (const float*)d_in[8];
    const float* W_mu  = (const float*)d_in[9];
    const float* b_mu  = (const float*)d_in[10];
    const float* W_lin = (const float*)d_in[11];
    const float* b_lin = (const float*)d_in[12];
    float* out = (float*)d_out;

    prep_kernel <<<D_MODEL, N_STATE>>>(log_a, B_ssm, C_ssm);
    decay_kernel<<<dim3(T_LEN/128, D_MODEL), 128>>>();
    gemm_kernel <<<dim3(NSPLIT, BATCH/8), 128>>>(in_chan, W_in);
    final_kernel<<<BATCH, D_MODEL>>>(in_chan, W_in, b_in, D_ssm,
                                     W_mu, b_mu, W_lin, b_lin, out);
}

// round 9
// speedup vs baseline: 2.1814x; 1.0742x over previous
#include <cuda_runtime.h>
#include <cuda_bf16.h>

// Problem constants (fixed shapes from reference)
#define T_LEN   4096
#define C_IN    8
#define BATCH   64
#define D_MODEL 128
#define N_STATE 64
#define HID     128
#define CB_ROWS (C_IN*BATCH)    // 512

// Decay negligibility threshold: terms with a^k < e^-THRESH are dropped.
// Tail bound: e^-34/(1-a_max) * |cb| * |u| * 64  ~ 1e-10 on y ~ O(1).
#define THRESH  34.0f

// GEMM tiling (R3 measured-best config)
#define NSPLIT  64
#define TSEG    (T_LEN/NSPLIT)  // 64
#define KC      16
#define RT      64

// Decay: each block covers 512 k (threads t-contiguous; 4 k per thread
// spaced 128 apart -> same coalescing as R3, 1/4 the exps and blocks)
#define DKB     512

// Scratch (no allocations allowed -> device globals, zero-initialized once)
__device__ float g_buf[T_LEN*D_MODEL];                 // g[t][d], 2 MB
__device__ float gs_buf[D_MODEL];                      // Gs[d]
__device__ float Y_part[NSPLIT*BATCH*D_MODEL];         // folded partials, 2 MB
__device__ float lna_tab[D_MODEL*N_STATE];             // ln(sigmoid(log_a))
__device__ float a128_tab[D_MODEL*N_STATE];            // a^128
__device__ float cb_tab[D_MODEL*N_STATE];              // C*B
__device__ int   kcut;                                 // max non-negligible k
// kcut via atomicMax w/o reset: inputs constant across graph replays ->
// monotone & identical every call (deterministic).

__device__ __forceinline__ int split_lo(int kc) {
    // smallest split s whose k-range [T-TSEG*(s+1), T-TSEG*s) intersects k<=kc
    int s0 = (T_LEN - kc + TSEG - 1) / TSEG - 1;
    return s0 < 0 ? 0 : s0;
}

// ---------------------------------------------------------------------------
// Kernel 0: tables + Gs[d] (exact geometric series) + global kcut.
// ---------------------------------------------------------------------------
__global__ void prep_kernel(const float* __restrict__ log_a,
                            const float* __restrict__ B_ssm,
                            const float* __restrict__ C_ssm) {
    const int d = blockIdx.x;
    const int n = threadIdx.x;

    float la  = log_a[d*N_STATE + n];
    float a   = 1.f / (1.f + expf(-la));     // accurate sigmoid
    float lna = logf(a);                     // < 0
    float cb  = C_ssm[d*N_STATE + n] * B_ssm[d*N_STATE + n];
    lna_tab [d*N_STATE + n] = lna;
    a128_tab[d*N_STATE + n] = __expf(128.f * lna);
    cb_tab  [d*N_STATE + n] = cb;

    int km = (lna > -1e-6f) ? T_LEN
                            : min(T_LEN, (int)(THRESH / -lna) + 1);

    float aT  = __expf((float)T_LEN * lna);
    float gsn = cb * (1.f - aT) / fmaxf(1.f - a, 1e-30f);

    __shared__ float gs_sh[N_STATE];
    __shared__ int   km_sh[N_STATE];
    gs_sh[n] = gsn;
    km_sh[n] = km;
    __syncthreads();
    if (n == 0) {
        float s = 0.f; int m = 0;
        #pragma unroll
        for (int i = 0; i < N_STATE; ++i) { s += gs_sh[i]; m = max(m, km_sh[i]); }
        gs_buf[d] = s;
        atomicMax(&kcut, m);
    }
}

// ---------------------------------------------------------------------------
// Kernel 1: g[d,t] = sum_n cb * a^(T-1-t). Block covers k in [kb, kb+512)
// for one d; thread owns k = kb+tid (+128j, j=0..3): one __expf anchor +
// chain-multiplies by a^128. Store pattern identical to the R3 kernel.
// Chunks beyond kcut never written: zero-init content IS the correct value.
// ---------------------------------------------------------------------------
__global__ void decay_kernel() {
    const int kb = blockIdx.x * DKB;
    if (kb > kcut) return;

    const int d   = blockIdx.y;
    const int tid = threadIdx.x;

    __shared__ float lna_s[N_STATE];
    __shared__ float f_s[N_STATE];
    __shared__ float cb_s[N_STATE];
    if (tid < N_STATE) {
        lna_s[tid] = lna_tab [d*N_STATE + tid];
        f_s[tid]   = a128_tab[d*N_STATE + tid];
        cb_s[tid]  = cb_tab  [d*N_STATE + tid];
    }
    __syncthreads();

    const float kbf = (float)kb;
    const float kf  = (float)(kb + tid);

    float acc0 = 0.f, acc1 = 0.f, acc2 = 0.f, acc3 = 0.f;
    #pragma unroll 4
    for (int n = 0; n < N_STATE; ++n) {
        float lna = lna_s[n];
        if (kbf * lna > -THRESH) {              // block-uniform per n
            float cb = cb_s[n];
            float f  = f_s[n];
            float e  = __expf(kf * lna);
            acc0 += cb * e; e *= f;             // k
            acc1 += cb * e; e *= f;             // k+128
            acc2 += cb * e; e *= f;             // k+256
            acc3 += cb * e;                     // k+384
        }
    }
    const int t0 = T_LEN - 1 - (kb + tid);
    g_buf[(t0      )*D_MODEL + d] = acc0;
    g_buf[(t0 - 128)*D_MODEL + d] = acc1;
    g_buf[(t0 - 256)*D_MODEL + d] = acc2;
    g_buf[(t0 - 384)*D_MODEL + d] = acc3;
}

// ---------------------------------------------------------------------------
// Kernel 2: fused GEMM + c-fold (unchanged from R7, the winning config).
// Block rows are B-MAJOR: local row r -> X row (r&7)*64 + b8 + (r>>3), so
// each thread's acc[8][8] holds all 8 c's for ONE b; the register epilogue
// folds sum_c m[b,c]*W_in[c,d]*P. Output: Y_part[split][b][128].
// ---------------------------------------------------------------------------
__global__ void __launch_bounds__(128) gemm_kernel(const float* __restrict__ X,
                                                   const float* __restrict__ W_in) {
    const int split = blockIdx.x;
    if (split < split_lo(kcut)) return;

    const int b8  = blockIdx.y * 8;
    const int tid = threadIdx.x;

    __shared__ __align__(16) float As[KC][RT];
    __shared__ __align__(16) float Bs[KC][D_MODEL];
    __shared__ __align__(16) float w_sh[C_IN][D_MODEL];
    __shared__ float m_sh[8][C_IN];

    #pragma unroll
    for (int i = 0; i < 8; ++i)
        ((float*)w_sh)[tid + i*128] = W_in[tid + i*128];
    if (tid < 64) {
        int c  = tid & 7;
        int bl = tid >> 3;
        m_sh[bl][c] = X[((c << 6) + b8 + bl)*T_LEN + (T_LEN - 1)];
    }

    float acc[8][8];
    #pragma unroll
    for (int i = 0; i < 8; ++i)
        #pragma unroll
        for (int j = 0; j < 8; ++j) acc[i][j] = 0.f;

    const int r0  = (tid >> 4) * 8;
    const int c0  = (tid & 15) * 8;
    const int ar  = tid >> 1;
    const int ak  = (tid & 1) * 8;
    const int bc  = (tid & 31) * 4;
    const int bk0 = tid >> 5;
    const int xrow = ((ar & 7) << 6) + b8 + (ar >> 3);

    #pragma unroll
    for (int ch = 0; ch < TSEG/KC; ++ch) {
        const int tb = split*TSEG + ch*KC;

        const float* asrc = X + xrow*T_LEN + tb + ak;
        float4 v0 = *(const float4*)asrc;
        float4 v1 = *(const float4*)(asrc + 4);
        As[ak+0][ar] = v0.x; As[ak+1][ar] = v0.y;
        As[ak+2][ar] = v0.z; As[ak+3][ar] = v0.w;
        As[ak+4][ar] = v1.x; As[ak+5][ar] = v1.y;
        As[ak+6][ar] = v1.z; As[ak+7][ar] = v1.w;

        #pragma unroll
        for (int it = 0; it < 4; ++it) {
            int kk = it*4 + bk0;
            *(float4*)&Bs[kk][bc] =
                *(const float4*)(g_buf + (tb + kk)*D_MODEL + bc);
        }
        __syncthreads();

        #pragma unroll
        for (int kk = 0; kk < KC; ++kk) {
            float4 a0 = *(const float4*)&As[kk][r0];
            float4 a1 = *(const float4*)&As[kk][r0+4];
            float4 b0 = *(const float4*)&Bs[kk][c0];
            float4 b1 = *(const float4*)&Bs[kk][c0+4];
            float av[8] = {a0.x,a0.y,a0.z,a0.w,a1.x,a1.y,a1.z,a1.w};
            float bv[8] = {b0.x,b0.y,b0.z,b0.w,b1.x,b1.y,b1.z,b1.w};
            #pragma unroll
            for (int i = 0; i < 8; ++i)
                #pragma unroll
                for (int j = 0; j < 8; ++j)
                    acc[i][j] += av[i] * bv[j];
        }
        __syncthreads();
    }

    const int bl = tid >> 4;
    float yo[8];
    #pragma unroll
    for (int j = 0; j < 8; ++j) yo[j] = 0.f;
    #pragma unroll
    for (int c = 0; c < C_IN; ++c) {
        float m = m_sh[bl][c];
        float4 w0 = *(const float4*)&w_sh[c][c0];
        float4 w1 = *(const float4*)&w_sh[c][c0+4];
        float wv[8] = {w0.x,w0.y,w0.z,w0.w, w1.x,w1.y,w1.z,w1.w};
        #pragma unroll
        for (int j = 0; j < 8; ++j)
            yo[j] += m * wv[j] * acc[c][j];
    }
    float* dst = Y_part + (split*BATCH + b8 + bl)*D_MODEL + c0;
    *(float4*)dst       = make_float4(yo[0], yo[1], yo[2], yo[3]);
    *(float4*)(dst + 4) = make_float4(yo[4], yo[5], yo[6], yo[7]);
}

// ---------------------------------------------------------------------------
// Kernel 3: epilogue, 512 threads per block (one block per batch b).
// Phase 1: split-sum over s parallelized across 4 s-groups x 128 d.
// Phase 2: z = gelu(y) @ W_mu parallelized across 4 dd-quarters x 128 h.
// Phase 3: out[b] = sigmoid(z . W_lin + b_lin).
// ---------------------------------------------------------------------------
__global__ void __launch_bounds__(512) final_kernel(
                             const float* __restrict__ in_chan,
                             const float* __restrict__ W_in,
                             const float* __restrict__ b_in,
                             const float* __restrict__ D_ssm,
                             const float* __restrict__ W_mu,
                             const float* __restrict__ b_mu,
                             const float* __restrict__ W_lin,
                             const float* __restrict__ b_lin,
                             float* __restrict__ out) {
    const int b   = blockIdx.x;
    const int tid = threadIdx.x;       // 0..511
    const int d   = tid & 127;
    const int sg  = tid >> 7;          // 0..3

    __shared__ float m_sh[C_IN];
    __shared__ float part[4][D_MODEL];
    __shared__ float ysh[D_MODEL];
    __shared__ float red[4];

    if (tid < C_IN)
        m_sh[tid] = in_chan[(tid*BATCH + b)*T_LEN + (T_LEN-1)];
    __syncthreads();

    // Phase 1: split-sum, s strided by 4 groups, 2-way ILP inside.
    {
        const int s0 = split_lo(kcut);
        const int stride = BATCH*D_MODEL;
        const float* yp = Y_part + b*D_MODEL + d;
        float a0 = 0.f, a1 = 0.f;
        int s = s0 + sg;
        for (; s + 4 < NSPLIT; s += 8) {
            a0 += yp[s*stride];
            a1 += yp[(s+4)*stride];
        }
        for (; s < NSPLIT; s += 4) a0 += yp[s*stride];
        part[sg][d] = a0 + a1;
    }
    __syncthreads();

    if (tid < D_MODEL) {
        float bi = b_in[tid];
        float y  = bi * gs_buf[tid]
                 + (part[0][tid] + part[1][tid])
                 + (part[2][tid] + part[3][tid]);
        float ul = bi;
        #pragma unroll
        for (int c = 0; c < C_IN; ++c)
            ul += m_sh[c] * m_sh[c] * W_in[c*D_MODEL + tid];
        y += D_ssm[tid] * ul;

        // gelu (tanh approximation, matching jax.nn.gelu default)
        float tg  = 0.7978845608028654f * (y + 0.044715f*y*y*y);
        ysh[tid]  = 0.5f * y * (1.f + tanhf(tg));
    }
    __syncthreads();

    // Phase 2: z[h=d] partial over dd quarter [sg*32, sg*32+32).
    {
        float z = 0.f;
        const int dd0 = sg * 32;
        #pragma unroll 8
        for (int i = 0; i < 32; ++i)
            z += ysh[dd0 + i] * W_mu[(dd0 + i)*HID + d];
        part[sg][d] = z;
    }
    __syncthreads();

    // Phase 3: dot with W_lin + sigmoid.
    if (tid < D_MODEL) {
        float zt = (part[0][tid] + part[1][tid])
                 + (part[2][tid] + part[3][tid]) + b_mu[tid];
        float v = zt * W_lin[tid];
        #pragma unroll
        for (int o = 16; o; o >>= 1)
            v += __shfl_down_sync(0xffffffffu, v, o);
        if ((tid & 31) == 0) red[tid >> 5] = v;
    }
    __syncthreads();
    if (tid == 0) {
        float s2 = red[0] + red[1] + red[2] + red[3] + b_lin[0];
        out[b] = 1.f / (1.f + expf(-s2));
    }
}

// ---------------------------------------------------------------------------
extern "C" void kernel_launch(void* const* d_in, const int* in_sizes, int n_in,
                              void* d_out, int out_size) {
    const float* in_chan = (const float*)d_in[0];
    // d_in[1] = h_0, d_in[2] = c_0 : unused (zeros)
    const float* W_in  = (const float*)d_in[3];
    const float* b_in  = (const float*)d_in[4];
    const float* log_a = (const float*)d_in[5];
    const float* B_ssm = (const float*)d_in[6];
    const float* C_ssm = (const float*)d_in[7];
    const float* D_ssm = (const float*)d_in[8];
    const float* W_mu  = (const float*)d_in[9];
    const float* b_mu  = (const float*)d_in[10];
    const float* W_lin = (const float*)d_in[11];
    const float* b_lin = (const float*)d_in[12];
    float* out = (float*)d_out;

    prep_kernel <<<D_MODEL, N_STATE>>>(log_a, B_ssm, C_ssm);
    decay_kernel<<<dim3(T_LEN/DKB, D_MODEL), 128>>>();
    gemm_kernel <<<dim3(NSPLIT, BATCH/8), 128>>>(in_chan, W_in);
    final_kernel<<<BATCH, 512>>>(in_chan, W_in, b_in, D_ssm,
                                 W_mu, b_mu, W_lin, b_lin, out);
}